// round 13
// baseline (speedup 1.0000x reference)
#include <cuda_runtime.h>
#include <cuda_fp16.h>
#include <cstdint>
#include <math.h>

// Problem constants
#define NCc 65536
#define NPc 32768
#define Dc  128
#define Hc  4
#define Cc  128
#define HCc 512
#define Bc  1024
#define Lc  4
#define BWc 7
#define SLOPEc 0.2f
#define EMAXc 65536

// ---------------- scratch (device globals) ----------------
__device__ __half g_cell [NCc * Dc];
__device__ __half g_piece[NPc * Dc];
__device__ __half g_xl0  [NPc * HCc];    // compact src rows
__device__ __half g_xl1  [NCc * HCc];
__device__ __half g_xl2  [NCc * HCc];
__device__ __half g_xr0  [NCc * HCc];    // compact dst rows (deg>=2)
__device__ __half g_xr1  [NCc * HCc];
__device__ __half g_xr2  [NCc * HCc];
__device__ float  g_sc   [3][EMAXc * Hc];   // p values, CSR order
__device__ float  g_den  [3][NCc * Hc];     // compact by dst rank
__device__ float  g_sums [Bc * Dc];
__device__ float  g_cnts [Bc];
__device__ __half g_wt   [24 * HCc * Dc];
// CSR / degree / compaction (dst side)
__device__ int    g_deg  [3][NCc];
__device__ int    g_cur  [3][NCc];
__device__ int    g_rs   [3][NCc + 1];
__device__ int    g_csrc [3][EMAXc];     // compact src id per CSR slot
__device__ int    g_pose [3][EMAXc];
__device__ int    g_rank [3][NCc];
__device__ int    g_list [3][NCc];
__device__ int    g_mc   [3];
// src side compaction
__device__ int    g_degs [3][NCc];
__device__ int    g_ranks[3][NCc];
__device__ int    g_lists[3][NCc];
__device__ int    g_ms   [3];
__device__ int    g_jt   [6];

// ---------------- helpers ----------------
__device__ __forceinline__ void mma_f16(float* c, const uint32_t* a, uint32_t b0, uint32_t b1) {
    asm volatile(
        "mma.sync.aligned.m16n8k16.row.col.f32.f16.f16.f32 "
        "{%0,%1,%2,%3}, {%4,%5,%6,%7}, {%8,%9}, {%0,%1,%2,%3};"
        : "+f"(c[0]), "+f"(c[1]), "+f"(c[2]), "+f"(c[3])
        : "r"(a[0]), "r"(a[1]), "r"(a[2]), "r"(a[3]), "r"(b0), "r"(b1));
}

// ---------------- weight prep ----------------
__global__ void k_wprep(const float* __restrict__ W, __half* __restrict__ WT) {
    __shared__ float t[32][33];
    int mat = blockIdx.z;
    int n0 = blockIdx.x * 32, k0 = blockIdx.y * 32;
    int x = threadIdx.x, y = threadIdx.y;
    const float* w  = W  + (size_t)mat * Dc * HCc;
    __half*      wt = WT + (size_t)mat * Dc * HCc;
#pragma unroll
    for (int j = 0; j < 4; j++)
        t[y + 8 * j][x] = w[(size_t)(k0 + y + 8 * j) * HCc + n0 + x];
    __syncthreads();
#pragma unroll
    for (int j = 0; j < 4; j++)
        wt[(size_t)(n0 + y + 8 * j) * Dc + k0 + x] = __float2half_rn(t[x][y + 8 * j]);
}

// ---------------- degree + CSR + compaction ----------------
struct DegB { const int* dst[3]; const int* src[3]; int E[3]; };
__global__ void k_hist(DegB D, int* __restrict__ deg, int* __restrict__ degs) {
    int z = blockIdx.z;
    int i = blockIdx.x * blockDim.x + threadIdx.x;
    if (i < D.E[z]) {
        atomicAdd(&deg[z * NCc + D.dst[z][i]], 1);
        atomicAdd(&degs[z * NCc + D.src[z][i]], 1);
    }
}
// dst side: CSR row starts + deg>=2 rank/list/mc + xr gemm tiles (jt odd slots)
__global__ void k_scan_all(const int* __restrict__ deg, int* __restrict__ rs,
                           int* __restrict__ rank, int* __restrict__ list,
                           int* __restrict__ mc, int* __restrict__ jt) {
    int z = blockIdx.x;
    const int* dg = deg + z * NCc;
    int* rsz = rs + z * (NCc + 1);
    int* rk  = rank + z * NCc;
    int* ls  = list + z * NCc;
    int t = threadIdx.x;            // 1024
    const int chunk = NCc >> 10;    // 64
    int base = t * chunk;
    int se = 0, s2 = 0;
#pragma unroll 4
    for (int i = 0; i < chunk; i++) {
        int v = dg[base + i];
        se += v; s2 += (v >= 2);
    }
    __shared__ int sme[1024], sm2[1024];
    sme[t] = se; sm2[t] = s2;
    __syncthreads();
    for (int off = 1; off < 1024; off <<= 1) {
        int ve = (t >= off) ? sme[t - off] : 0;
        int v2 = (t >= off) ? sm2[t - off] : 0;
        __syncthreads();
        sme[t] += ve; sm2[t] += v2;
        __syncthreads();
    }
    int rune = sme[t] - se, run2 = sm2[t] - s2;
    for (int i = 0; i < chunk; i++) {
        int g = base + i;
        int v = dg[g];
        rsz[g] = rune; rune += v;
        if (v >= 2) { rk[g] = run2; ls[run2] = g; run2++; }
        else rk[g] = -1;
    }
    if (t == 1023) {
        rsz[NCc] = rune;
        mc[z] = run2;
        jt[2 * z + 1] = (run2 + 127) / 128;
    }
}
// src side: deg>=1 rank/list/ms + xl gemm tiles (jt even slots)
__global__ void k_scan_src(const int* __restrict__ degs, int* __restrict__ ranks,
                           int* __restrict__ lists, int* __restrict__ ms,
                           int* __restrict__ jt) {
    int z = blockIdx.x;
    int n = (z == 0) ? NPc : NCc;
    const int* dg = degs + z * NCc;
    int* rk = ranks + z * NCc;
    int* ls = lists + z * NCc;
    int t = threadIdx.x;            // 1024
    int chunk = n >> 10;            // 32 or 64
    int base = t * chunk;
    int s1 = 0;
#pragma unroll 4
    for (int i = 0; i < chunk; i++) s1 += (dg[base + i] >= 1);
    __shared__ int sm[1024];
    sm[t] = s1;
    __syncthreads();
    for (int off = 1; off < 1024; off <<= 1) {
        int v = (t >= off) ? sm[t - off] : 0;
        __syncthreads();
        sm[t] += v;
        __syncthreads();
    }
    int run = sm[t] - s1;
    for (int i = 0; i < chunk; i++) {
        int g = base + i;
        if (dg[g] >= 1) { rk[g] = run; ls[run] = g; run++; }
        else rk[g] = -1;
    }
    if (t == 1023) {
        ms[z] = run;
        jt[2 * z] = (run + 127) / 128;
    }
}
struct ScatB { const int* dst[3]; const int* src[3]; const int* ranks[3];
               int* rs[3]; int* cur[3]; int* csrc[3]; int* pose[3]; int E[3]; };
__global__ void k_scatter(ScatB C) {
    int z = blockIdx.z;
    int i = blockIdx.x * blockDim.x + threadIdx.x;
    if (i < C.E[z]) {
        int d = C.dst[z][i];
        int pos = C.rs[z][d] + atomicAdd(&C.cur[z][d], 1);
        C.csrc[z][pos] = C.ranks[z][C.src[z][i]];   // compact src id
        C.pose[z][i] = pos;
    }
}

// ---------------- batched strip-mined fp16 GEMM, optional row gather ----------------
struct GemmJob {
    const __half* A; const __half* W; const float* bias; __half* out;
    const int* rows; const int* tilesPtr; const int* McPtr;
};
struct GemmBatch { GemmJob j[6]; };

#define LDH 136
__global__ __launch_bounds__(512, 1)
void k_gemm(GemmBatch P) {
    extern __shared__ __half smh[];
    const GemmJob jb = P.j[blockIdx.z];
    int tiles = __ldg(jb.tilesPtr);
    int t = blockIdx.y;
    if (t >= tiles) return;
    const int GY = gridDim.y;
    int Mv = __ldg(jb.McPtr);

    __half* Bs  = smh;
    __half* As0 = smh + 128 * LDH;
    __half* As1 = As0 + 128 * LDH;
    uint32_t bsAddr   = (uint32_t)__cvta_generic_to_shared(Bs);
    uint32_t aAddr[2] = {(uint32_t)__cvta_generic_to_shared(As0),
                         (uint32_t)__cvta_generic_to_shared(As1)};

    int tid = threadIdx.x;
    int n0 = blockIdx.x * 128;

    {
        const __half* Wp = jb.W + (size_t)n0 * Dc;
#pragma unroll
        for (int it = 0; it < 4; it++) {
            int idx = tid + it * 512;
            int r = idx >> 4, ch = idx & 15;
            uint32_t d = bsAddr + (uint32_t)((r * LDH + ch * 8) * 2);
            asm volatile("cp.async.cg.shared.global [%0], [%1], 16;"
                         :: "r"(d), "l"(Wp + r * Dc + ch * 8));
        }
    }
    auto issueA = [&](int tile, int buf) {
#pragma unroll
        for (int it = 0; it < 4; it++) {
            int idx = tid + it * 512;
            int r = idx >> 4, ch = idx & 15;
            int gr = tile * 128 + r;
            int cg = gr < Mv ? gr : Mv - 1;
            const __half* Ap = jb.A + (size_t)__ldg(&jb.rows[cg]) * Dc;
            uint32_t d = aAddr[buf] + (uint32_t)((r * LDH + ch * 8) * 2);
            asm volatile("cp.async.cg.shared.global [%0], [%1], 16;"
                         :: "r"(d), "l"(Ap + ch * 8));
        }
    };
    issueA(t, 0);
    asm volatile("cp.async.commit_group;" ::: "memory");
    asm volatile("cp.async.wait_group 0;" ::: "memory");
    __syncthreads();

    int lane = tid & 31, wid = tid >> 5;
    int wm = (wid & 3) * 32, wn = (wid >> 2) * 32;
    int gid = lane >> 2, tig = lane & 3;

    uint32_t aoff[2], boff[2];
#pragma unroll
    for (int mt = 0; mt < 2; mt++)
        aoff[mt] = (uint32_t)(((wm + mt * 16 + (lane & 15)) * LDH + (lane >> 4) * 8) * 2);
#pragma unroll
    for (int p = 0; p < 2; p++)
        boff[p] = bsAddr + (uint32_t)(((wn + p * 16 + ((lane >> 4) << 3) + (lane & 7)) * LDH
                                      + ((lane >> 3) & 1) * 8) * 2);

#define LDFRAG(st, ks) do { \
    uint32_t kb = (uint32_t)((ks) * 32); \
    _Pragma("unroll") \
    for (int mt = 0; mt < 2; mt++) \
        asm volatile("ldmatrix.sync.aligned.m8n8.x4.shared.b16 {%0,%1,%2,%3}, [%4];" \
            : "=r"(af[st][mt][0]), "=r"(af[st][mt][1]), "=r"(af[st][mt][2]), "=r"(af[st][mt][3]) \
            : "r"(aCur + aoff[mt] + kb)); \
    _Pragma("unroll") \
    for (int p = 0; p < 2; p++) \
        asm volatile("ldmatrix.sync.aligned.m8n8.x4.shared.b16 {%0,%1,%2,%3}, [%4];" \
            : "=r"(bf[st][p][0]), "=r"(bf[st][p][1]), "=r"(bf[st][p][2]), "=r"(bf[st][p][3]) \
            : "r"(boff[p] + kb)); \
} while (0)

    int buf = 0;
    for (;;) {
        int tn = t + GY;
        if (tn < tiles) {
            issueA(tn, buf ^ 1);
            asm volatile("cp.async.commit_group;" ::: "memory");
        }
        uint32_t aCur = aAddr[buf];
        float acc[2][4][4];
#pragma unroll
        for (int mt = 0; mt < 2; mt++)
#pragma unroll
            for (int nt = 0; nt < 4; nt++)
#pragma unroll
                for (int q = 0; q < 4; q++) acc[mt][nt][q] = 0.f;

        uint32_t af[2][2][4], bf[2][2][4];
        LDFRAG(0, 0);
#pragma unroll
        for (int ks = 0; ks < 8; ks++) {
            int cu = ks & 1;
            if (ks < 7) LDFRAG(cu ^ 1, ks + 1);
#pragma unroll
            for (int mt = 0; mt < 2; mt++)
#pragma unroll
                for (int nt = 0; nt < 4; nt++) {
                    int p = nt >> 1, s = (nt & 1) * 2;
                    mma_f16(acc[mt][nt], af[cu][mt], bf[cu][p][s], bf[cu][p][s + 1]);
                }
        }
        int tm0 = t * 128;
#pragma unroll
        for (int mt = 0; mt < 2; mt++) {
            int r0 = tm0 + wm + mt * 16 + gid;
#pragma unroll
            for (int nt = 0; nt < 4; nt++) {
                int col = n0 + wn + nt * 8 + tig * 2;
                float2 bv = *(const float2*)&jb.bias[col];
                __half2 h0 = __floats2half2_rn(acc[mt][nt][0] + bv.x, acc[mt][nt][1] + bv.y);
                __half2 h1 = __floats2half2_rn(acc[mt][nt][2] + bv.x, acc[mt][nt][3] + bv.y);
                __stcs((unsigned int*)&jb.out[(size_t)r0 * HCc + col], *(unsigned int*)&h0);
                __stcs((unsigned int*)&jb.out[(size_t)(r0 + 8) * HCc + col], *(unsigned int*)&h1);
            }
        }
        if (tn >= tiles) break;
        asm volatile("cp.async.wait_group 0;" ::: "memory");
        __syncthreads();
        t = tn; buf ^= 1;
    }
#undef LDFRAG
}

// ---------------- misc ----------------
__global__ void k_zero4(float4* __restrict__ p, int n4) {
    int i = blockIdx.x * blockDim.x + threadIdx.x;
    if (i < n4) p[i] = make_float4(0.f, 0.f, 0.f, 0.f);
}
__global__ void k_iota(int* __restrict__ p, int n) {
    int i = blockIdx.x * blockDim.x + threadIdx.x;
    if (i < n) p[i] = i;
}
__global__ void k_embed(const int* __restrict__ idx, const float4* __restrict__ emb,
                        __half2* __restrict__ out, int n4) {
    int i = blockIdx.x * blockDim.x + threadIdx.x;
    if (i < n4) {
        float4 v = emb[idx[i >> 5] * 32 + (i & 31)];
        out[2 * i]     = __floats2half2_rn(v.x, v.y);
        out[2 * i + 1] = __floats2half2_rn(v.z, v.w);
    }
}

// ---------------- fused score+exp+denom (active edges only) ----------------
struct ScoreB {
    const int* src[3]; const int* dst[3]; const int* pose[3];
    const int* ranks[3];                 // src compact rank
    const __half* xl[3]; const __half* xr[3];
    const float* att[3];
    const int* deg[3]; const int* rank[3];
    float* sc[3]; float* den[3];
    int E[3];
};
__global__ void k_scorep(ScoreB P) {
    int z = blockIdx.z;
    int e = blockIdx.x * (blockDim.x >> 5) + (threadIdx.x >> 5);
    int lane = threadIdx.x & 31;
    if (e >= P.E[z]) return;
    int d = P.dst[z][e];
    if (P.deg[z][d] < 2) return;
    int sr = P.ranks[z][P.src[z][e]];
    int rk = P.rank[z][d];
    int pos = P.pose[z][e];
    const __half2* xls = (const __half2*)P.xl[z] + (size_t)sr * 256;
    const __half2* xrd = (const __half2*)P.xr[z] + (size_t)rk * 256;
    const float* att = P.att[z];
    float part[4] = {0.f, 0.f, 0.f, 0.f};
#pragma unroll
    for (int h = 0; h < 4; h++)
#pragma unroll
        for (int k = 0; k < 2; k++) {
            int idx = h * 64 + k * 32 + lane;
            float2 a2 = __half22float2(xls[idx]);
            float2 b2 = __half22float2(xrd[idx]);
            float vx = a2.x + b2.x, vy = a2.y + b2.y;
            vx = vx > 0.f ? vx : SLOPEc * vx;
            vy = vy > 0.f ? vy : SLOPEc * vy;
            float2 at = *(const float2*)&att[2 * idx];
            part[h] += vx * at.x + vy * at.y;
        }
#pragma unroll
    for (int h = 0; h < 4; h++) {
        float v = part[h];
#pragma unroll
        for (int off = 16; off; off >>= 1) v += __shfl_down_sync(0xffffffffu, v, off);
        if (lane == 0) {
            float p = __expf(v);
            P.sc[z][pos * 4 + h] = p;
            atomicAdd(&P.den[z][rk * 4 + h], p);
        }
    }
}

// ---------------- CSR gather aggregation (1 warp per dst) + bias + relu -> cell ----------------
struct AggB {
    const int* rs[3]; const int* csrc[3];
    const __half* xl[3];
    const float* sc[3]; float* den[3];
    const int* rank[3];
    const float* cb;
    __half* cell;
};
__global__ __launch_bounds__(256)
void k_aggr_g(AggB P) {
    int wid = threadIdx.x >> 5, lane = threadIdx.x & 31;
    int d = blockIdx.x * 8 + wid;
    float tot[4] = {0.f, 0.f, 0.f, 0.f};
#pragma unroll
    for (int r = 0; r < 3; r++) {
        int beg = P.rs[r][d], end = P.rs[r][d + 1];
        if (beg >= end) continue;
        const __half2* xlp = (const __half2*)P.xl[r];
        if (end - beg == 1) {
            const __half2* xls = xlp + (size_t)P.csrc[r][beg] * 256;
#pragma unroll
            for (int h = 0; h < 4; h++) {
                float2 a0 = __half22float2(xls[h * 64 + lane]);
                float2 a1 = __half22float2(xls[h * 64 + 32 + lane]);
                tot[0] += 0.25f * a0.x; tot[1] += 0.25f * a0.y;
                tot[2] += 0.25f * a1.x; tot[3] += 0.25f * a1.y;
            }
        } else {
            int rk = P.rank[r][d];
            float* denp = P.den[r] + rk * 4;
            float rc[4];
#pragma unroll
            for (int h = 0; h < 4; h++) rc[h] = 0.25f / (denp[h] + 1e-16f);
            if (lane < 4) denp[lane] = 0.f;   // reset for next layer (sole owner)
            const float* scp = P.sc[r];
            for (int e = beg; e < end; e++) {
                const __half2* xls = xlp + (size_t)P.csrc[r][e] * 256;
                float al[4];
#pragma unroll
                for (int h = 0; h < 4; h++) al[h] = scp[e * 4 + h] * rc[h];
#pragma unroll
                for (int h = 0; h < 4; h++) {
                    float2 a0 = __half22float2(xls[h * 64 + lane]);
                    float2 a1 = __half22float2(xls[h * 64 + 32 + lane]);
                    tot[0] += al[h] * a0.x; tot[1] += al[h] * a0.y;
                    tot[2] += al[h] * a1.x; tot[3] += al[h] * a1.y;
                }
            }
        }
    }
    int c0 = 2 * lane, c2 = 64 + 2 * lane;
    const float* cb = P.cb;
    float b0 = cb[c0] + cb[128 + c0] + cb[256 + c0];
    float b1 = cb[c0 + 1] + cb[128 + c0 + 1] + cb[256 + c0 + 1];
    float b2 = cb[c2] + cb[128 + c2] + cb[256 + c2];
    float b3 = cb[c2 + 1] + cb[128 + c2 + 1] + cb[256 + c2 + 1];
    __half2* cp = (__half2*)P.cell + (size_t)d * 64;
    cp[lane]      = __floats2half2_rn(fmaxf(tot[0] + b0, 0.f), fmaxf(tot[1] + b1, 0.f));
    cp[32 + lane] = __floats2half2_rn(fmaxf(tot[2] + b2, 0.f), fmaxf(tot[3] + b3, 0.f));
}

// ---------------- pooling ----------------
__global__ void k_pool(const __half* __restrict__ cell, const int* __restrict__ batch,
                       float* __restrict__ sums, float* __restrict__ cnts) {
    __shared__ __half sc[64 * 128];
    __shared__ int sb[64];
    int g = blockIdx.x;
    int tid = threadIdx.x;  // 128
    const int4* src = (const int4*)(cell + (size_t)g * 64 * 128);
    int4* dst = (int4*)sc;
#pragma unroll
    for (int i = 0; i < 8; i++) dst[tid + i * 128] = src[tid + i * 128];
    if (tid < 64) sb[tid] = batch[g * 64 + tid];
    __syncthreads();
    float a = 0.f, c = 0.f;
#pragma unroll 4
    for (int r = 0; r < 64; r++) {
        a += __half2float(sc[r * 128 + tid]);
        c += 1.f;
        if (r == 63 || sb[r + 1] != sb[r]) {
            atomicAdd(&sums[(size_t)sb[r] * Dc + tid], a);
            if (tid == 0) atomicAdd(&cnts[sb[r]], c);
            a = 0.f; c = 0.f;
        }
    }
}

// ---------------- heads ----------------
__global__ void k_head(const float* __restrict__ sums, const float* __restrict__ cnts,
                       const float* __restrict__ fc1W, const float* __restrict__ fc1b,
                       const float* __restrict__ polW, const float* __restrict__ polb,
                       const float* __restrict__ valW, const float* __restrict__ valb,
                       float* __restrict__ out_policy, float* __restrict__ out_value) {
    int b = blockIdx.x;
    int t = threadIdx.x;  // 64
    __shared__ float pooled[128];
    __shared__ float hsh[64];
    float cnt = fmaxf(cnts[b], 1.f);
    pooled[t]      = sums[b * Dc + t] / cnt;
    pooled[t + 64] = sums[b * Dc + 64 + t] / cnt;
    __syncthreads();
    float a = fc1b[t];
#pragma unroll 4
    for (int d = 0; d < 128; d++) a += pooled[d] * fc1W[d * 64 + t];
    hsh[t] = fmaxf(a, 0.f);
    __syncthreads();
    if (t < BWc) {
        float a2 = polb[t];
#pragma unroll 4
        for (int k = 0; k < 64; k++) a2 += hsh[k] * polW[k * BWc + t];
        out_policy[b * BWc + t] = a2;
    }
    if (t == 8) {
        float a2 = valb[0];
#pragma unroll 4
        for (int k = 0; k < 64; k++) a2 += hsh[k] * valW[k];
        out_value[b] = tanhf(a2);
    }
}

// ---------------- launch ----------------
extern "C" void kernel_launch(void* const* d_in, const int* in_sizes, int n_in,
                              void* d_out, int out_size) {
    const int* cell_x     = (const int*)d_in[0];
    const int* piece_x    = (const int*)d_in[1];
    const int* srcs[3]    = {(const int*)d_in[2], (const int*)d_in[4], (const int*)d_in[6]};
    const int* dsts[3]    = {(const int*)d_in[3], (const int*)d_in[5], (const int*)d_in[7]};
    const int  Es[3]      = {in_sizes[2], in_sizes[4], in_sizes[6]};
    const int* cell_batch = (const int*)d_in[8];
    const float* cell_emb  = (const float*)d_in[9];
    const float* piece_emb = (const float*)d_in[10];
    const float* Wl  = (const float*)d_in[11];
    const float* bl  = (const float*)d_in[12];
    const float* Wr  = (const float*)d_in[13];
    const float* br  = (const float*)d_in[14];
    const float* att = (const float*)d_in[15];
    const float* cb  = (const float*)d_in[16];
    const float* fc1W = (const float*)d_in[17];
    const float* fc1b = (const float*)d_in[18];
    const float* polW = (const float*)d_in[19];
    const float* polb = (const float*)d_in[20];
    const float* valW = (const float*)d_in[21];
    const float* valb = (const float*)d_in[22];

    const int NC = in_sizes[0];
    const int NP = in_sizes[1];

    float *p_sums, *p_cnts, *p_sc, *p_den;
    __half *p_cell, *p_piece, *p_wt;
    __half *p_xl[3], *p_xr[3];
    int *p_deg, *p_cur, *p_rs, *p_csrc, *p_pose, *p_rank, *p_list, *p_mc, *p_jt;
    int *p_degs, *p_ranks, *p_lists, *p_ms;
    cudaGetSymbolAddress((void**)&p_cell,  g_cell);
    cudaGetSymbolAddress((void**)&p_piece, g_piece);
    cudaGetSymbolAddress((void**)&p_xl[0], g_xl0);
    cudaGetSymbolAddress((void**)&p_xl[1], g_xl1);
    cudaGetSymbolAddress((void**)&p_xl[2], g_xl2);
    cudaGetSymbolAddress((void**)&p_xr[0], g_xr0);
    cudaGetSymbolAddress((void**)&p_xr[1], g_xr1);
    cudaGetSymbolAddress((void**)&p_xr[2], g_xr2);
    cudaGetSymbolAddress((void**)&p_sc,    g_sc);
    cudaGetSymbolAddress((void**)&p_den,   g_den);
    cudaGetSymbolAddress((void**)&p_sums,  g_sums);
    cudaGetSymbolAddress((void**)&p_cnts,  g_cnts);
    cudaGetSymbolAddress((void**)&p_wt,    g_wt);
    cudaGetSymbolAddress((void**)&p_deg,   g_deg);
    cudaGetSymbolAddress((void**)&p_cur,   g_cur);
    cudaGetSymbolAddress((void**)&p_rs,    g_rs);
    cudaGetSymbolAddress((void**)&p_csrc,  g_csrc);
    cudaGetSymbolAddress((void**)&p_pose,  g_pose);
    cudaGetSymbolAddress((void**)&p_rank,  g_rank);
    cudaGetSymbolAddress((void**)&p_list,  g_list);
    cudaGetSymbolAddress((void**)&p_mc,    g_mc);
    cudaGetSymbolAddress((void**)&p_jt,    g_jt);
    cudaGetSymbolAddress((void**)&p_degs,  g_degs);
    cudaGetSymbolAddress((void**)&p_ranks, g_ranks);
    cudaGetSymbolAddress((void**)&p_lists, g_lists);
    cudaGetSymbolAddress((void**)&p_ms,    g_ms);

    const int SMEM_GEMM = 3 * 128 * LDH * 2;
    cudaFuncSetAttribute(k_gemm, cudaFuncAttributeMaxDynamicSharedMemorySize, SMEM_GEMM);

    const int T = 256;
    const size_t MATSZ = (size_t)Dc * HCc;

    // ---- weight prep + embeddings ----
    k_wprep<<<dim3(16, 4, 12), dim3(32, 8)>>>(Wl, p_wt);
    k_wprep<<<dim3(16, 4, 12), dim3(32, 8)>>>(Wr, p_wt + 12 * MATSZ);
    k_embed<<<(NC * 32 + T - 1) / T, T>>>(cell_x, (const float4*)cell_emb, (__half2*)p_cell, NC * 32);
    k_embed<<<(NP * 32 + T - 1) / T, T>>>(piece_x, (const float4*)piece_emb, (__half2*)p_piece, NP * 32);

    // ---- degrees + CSR + compaction (edges static) ----
    DegB db;
    int Emax = 0;
    for (int r = 0; r < 3; r++) {
        db.dst[r] = dsts[r]; db.src[r] = srcs[r]; db.E[r] = Es[r];
        if (Es[r] > Emax) Emax = Es[r];
    }
    k_zero4<<<(3 * NCc / 4 + T - 1) / T, T>>>((float4*)p_deg, 3 * NCc / 4);
    k_zero4<<<(3 * NCc / 4 + T - 1) / T, T>>>((float4*)p_cur, 3 * NCc / 4);
    k_zero4<<<(3 * NCc / 4 + T - 1) / T, T>>>((float4*)p_degs, 3 * NCc / 4);
    k_zero4<<<(3 * NCc * Hc / 4 + T - 1) / T, T>>>((float4*)p_den, 3 * NCc * Hc / 4);
    k_hist<<<dim3((Emax + T - 1) / T, 1, 3), T>>>(db, p_deg, p_degs);
    k_scan_all<<<3, 1024>>>(p_deg, p_rs, p_rank, p_list, p_mc, p_jt);
    k_scan_src<<<3, 1024>>>(p_degs, p_ranks, p_lists, p_ms, p_jt);
    ScatB sbb;
    for (int r = 0; r < 3; r++) {
        sbb.dst[r] = dsts[r]; sbb.src[r] = srcs[r];
        sbb.ranks[r] = p_ranks + (size_t)r * NCc;
        sbb.rs[r]   = p_rs   + (size_t)r * (NCc + 1);
        sbb.cur[r]  = p_cur  + (size_t)r * NCc;
        sbb.csrc[r] = p_csrc + (size_t)r * EMAXc;
        sbb.pose[r] = p_pose + (size_t)r * EMAXc;
        sbb.E[r] = Es[r];
    }
    k_scatter<<<dim3((Emax + T - 1) / T, 1, 3), T>>>(sbb);

    // ---- layers ----
    for (int l = 0; l < Lc; l++) {
        GemmBatch gb;
        for (int z = 0; z < 6; z++) {
            int r = (z == 0 || z == 1) ? 0 : (z <= 3 ? 1 : 2);
            bool isL = (z == 0) || (z == 2) || (z == 4);
            int mat = l * 3 + r;
            gb.j[z].A        = (z == 0) ? p_piece : p_cell;
            gb.j[z].W        = p_wt + (isL ? mat : 12 + mat) * MATSZ;
            gb.j[z].bias     = (isL ? bl : br) + (size_t)mat * HCc;
            gb.j[z].out      = isL ? p_xl[r] : p_xr[r];
            gb.j[z].rows     = isL ? (p_lists + (size_t)r * NCc) : (p_list + (size_t)r * NCc);
            gb.j[z].tilesPtr = p_jt + z;
            gb.j[z].McPtr    = isL ? (p_ms + r) : (p_mc + r);
        }
        k_gemm<<<dim3(4, 37, 6), 512, SMEM_GEMM>>>(gb);

        ScoreB eb;
        for (int r = 0; r < 3; r++) {
            eb.src[r] = srcs[r]; eb.dst[r] = dsts[r];
            eb.pose[r] = p_pose + (size_t)r * EMAXc;
            eb.ranks[r] = p_ranks + (size_t)r * NCc;
            eb.xl[r] = p_xl[r]; eb.xr[r] = p_xr[r];
            eb.att[r] = att + (size_t)(l * 3 + r) * HCc;
            eb.deg[r]  = p_deg  + (size_t)r * NCc;
            eb.rank[r] = p_rank + (size_t)r * NCc;
            eb.sc[r]  = p_sc  + (size_t)r * EMAXc * Hc;
            eb.den[r] = p_den + (size_t)r * NCc * Hc;
            eb.E[r] = Es[r];
        }
        int wpb = T / 32;
        k_scorep<<<dim3((Emax + wpb - 1) / wpb, 1, 3), T>>>(eb);

        AggB ab;
        for (int r = 0; r < 3; r++) {
            ab.rs[r]   = p_rs   + (size_t)r * (NCc + 1);
            ab.csrc[r] = p_csrc + (size_t)r * EMAXc;
            ab.xl[r]   = p_xl[r];
            ab.sc[r]   = p_sc  + (size_t)r * EMAXc * Hc;
            ab.den[r]  = p_den + (size_t)r * NCc * Hc;
            ab.rank[r] = p_rank + (size_t)r * NCc;
        }
        ab.cb   = cb + (size_t)l * 3 * Cc;
        ab.cell = p_cell;
        k_aggr_g<<<NC / 8, 256>>>(ab);
    }

    // ---- pool + heads ----
    k_zero4<<<(Bc * 32 + T - 1) / T, T>>>((float4*)p_sums, Bc * 32);
    k_zero4<<<(Bc / 4 + T - 1) / T, T>>>((float4*)p_cnts, Bc / 4);
    k_pool<<<NC / 64, 128>>>(p_cell, cell_batch, p_sums, p_cnts);

    float* out = (float*)d_out;
    k_head<<<Bc, 64>>>(p_sums, p_cnts, fc1W, fc1b, polW, polb, valW, valb,
                       out, out + (size_t)Bc * BWc);
}

// round 14
// speedup vs baseline: 1.0831x; 1.0831x over previous
#include <cuda_runtime.h>
#include <cuda_fp16.h>
#include <cstdint>
#include <math.h>

// Problem constants
#define NCc 65536
#define NPc 32768
#define Dc  128
#define Hc  4
#define Cc  128
#define HCc 512
#define Bc  1024
#define Lc  4
#define BWc 7
#define SLOPEc 0.2f
#define EMAXc 65536

// ---------------- scratch (device globals) ----------------
__device__ __half g_cell [NCc * Dc];
__device__ __half g_piece[NPc * Dc];
__device__ __half g_xl0  [NPc * HCc];
__device__ __half g_xl1  [NCc * HCc];
__device__ __half g_xl2  [NCc * HCc];
__device__ __half g_xr0  [NCc * HCc];   // compact rows (deg>=2 dsts)
__device__ __half g_xr1  [NCc * HCc];
__device__ __half g_xr2  [NCc * HCc];
__device__ float  g_sc   [3][EMAXc * Hc];   // p values, CSR order
__device__ float  g_den  [3][NCc * Hc];     // compact by rank
__device__ float  g_sums [Bc * Dc];
__device__ float  g_cnts [Bc];
__device__ __half g_wt   [24 * HCc * Dc];
// CSR / degree / compaction
__device__ int    g_deg  [3][NCc];
__device__ int    g_cur  [3][NCc];
__device__ int    g_rs   [3][NCc + 1];
__device__ int    g_csrc [3][EMAXc];
__device__ int    g_rank [3][NCc];
__device__ int    g_list [3][NCc];
__device__ int    g_mc   [3];
__device__ int    g_jt   [6];
// active-edge compaction (deg[dst]>=2 edges only)
__device__ int    g_aes  [3][EMAXc];   // src
__device__ int    g_aer  [3][EMAXc];   // dst rank
__device__ int    g_aep  [3][EMAXc];   // CSR pos
__device__ int    g_na   [3];          // counts

// ---------------- helpers ----------------
__device__ __forceinline__ void mma_f16(float* c, const uint32_t* a, uint32_t b0, uint32_t b1) {
    asm volatile(
        "mma.sync.aligned.m16n8k16.row.col.f32.f16.f16.f32 "
        "{%0,%1,%2,%3}, {%4,%5,%6,%7}, {%8,%9}, {%0,%1,%2,%3};"
        : "+f"(c[0]), "+f"(c[1]), "+f"(c[2]), "+f"(c[3])
        : "r"(a[0]), "r"(a[1]), "r"(a[2]), "r"(a[3]), "r"(b0), "r"(b1));
}

// ---------------- weight prep ----------------
__global__ void k_wprep(const float* __restrict__ W, __half* __restrict__ WT) {
    __shared__ float t[32][33];
    int mat = blockIdx.z;
    int n0 = blockIdx.x * 32, k0 = blockIdx.y * 32;
    int x = threadIdx.x, y = threadIdx.y;
    const float* w  = W  + (size_t)mat * Dc * HCc;
    __half*      wt = WT + (size_t)mat * Dc * HCc;
#pragma unroll
    for (int j = 0; j < 4; j++)
        t[y + 8 * j][x] = w[(size_t)(k0 + y + 8 * j) * HCc + n0 + x];
    __syncthreads();
#pragma unroll
    for (int j = 0; j < 4; j++)
        wt[(size_t)(n0 + y + 8 * j) * Dc + k0 + x] = __float2half_rn(t[x][y + 8 * j]);
}

// ---------------- degree + CSR + compaction ----------------
struct DegB { const int* dst[3]; const int* src[3]; int E[3]; };
__global__ void k_hist(DegB D, int* __restrict__ deg) {
    int z = blockIdx.z;
    int i = blockIdx.x * blockDim.x + threadIdx.x;
    if (i < D.E[z]) atomicAdd(&deg[z * NCc + D.dst[z][i]], 1);
}
__global__ void k_jt_init(int* __restrict__ jt, int* __restrict__ na) {
    jt[0] = NPc / 128; jt[2] = NCc / 128; jt[4] = NCc / 128;
    na[0] = na[1] = na[2] = 0;
}
__global__ void k_scan_all(const int* __restrict__ deg, int* __restrict__ rs,
                           int* __restrict__ rank, int* __restrict__ list,
                           int* __restrict__ mc, int* __restrict__ jt) {
    int z = blockIdx.x;
    const int* dg = deg + z * NCc;
    int* rsz = rs + z * (NCc + 1);
    int* rk  = rank + z * NCc;
    int* ls  = list + z * NCc;
    int t = threadIdx.x;            // 1024
    const int chunk = NCc >> 10;    // 64
    int base = t * chunk;
    int se = 0, s2 = 0;
#pragma unroll 4
    for (int i = 0; i < chunk; i++) {
        int v = dg[base + i];
        se += v; s2 += (v >= 2);
    }
    __shared__ int sme[1024], sm2[1024];
    sme[t] = se; sm2[t] = s2;
    __syncthreads();
    for (int off = 1; off < 1024; off <<= 1) {
        int ve = (t >= off) ? sme[t - off] : 0;
        int v2 = (t >= off) ? sm2[t - off] : 0;
        __syncthreads();
        sme[t] += ve; sm2[t] += v2;
        __syncthreads();
    }
    int rune = sme[t] - se, run2 = sm2[t] - s2;
    for (int i = 0; i < chunk; i++) {
        int g = base + i;
        int v = dg[g];
        rsz[g] = rune; rune += v;
        if (v >= 2) { rk[g] = run2; ls[run2] = g; run2++; }
        else rk[g] = -1;
    }
    if (t == 1023) {
        rsz[NCc] = rune;
        mc[z] = run2;
        jt[2 * z + 1] = (run2 + 127) / 128;
    }
}
struct ScatB {
    const int* dst[3]; const int* src[3];
    const int* deg[3]; const int* rank[3];
    int* rs[3]; int* cur[3]; int* csrc[3];
    int* aes[3]; int* aer[3]; int* aep[3]; int* na;
    int E[3];
};
__global__ void k_scatter(ScatB C) {
    int z = blockIdx.z;
    int i = blockIdx.x * blockDim.x + threadIdx.x;
    if (i < C.E[z]) {
        int d = C.dst[z][i];
        int s = C.src[z][i];
        int pos = C.rs[z][d] + atomicAdd(&C.cur[z][d], 1);
        C.csrc[z][pos] = s;
        if (C.deg[z][d] >= 2) {
            int a = atomicAdd(&C.na[z], 1);
            C.aes[z][a] = s;
            C.aer[z][a] = C.rank[z][d];
            C.aep[z][a] = pos;
        }
    }
}

// ---------------- batched strip-mined fp16 GEMM, optional row gather ----------------
struct GemmJob {
    const __half* A; const __half* W; const float* bias; __half* out;
    const int* rows; const int* tilesPtr; const int* McPtr;
};
struct GemmBatch { GemmJob j[6]; };

#define LDH 136
__global__ __launch_bounds__(512, 1)
void k_gemm(GemmBatch P) {
    extern __shared__ __half smh[];
    const GemmJob jb = P.j[blockIdx.z];
    int tiles = __ldg(jb.tilesPtr);
    int t = blockIdx.y;
    if (t >= tiles) return;
    const int GY = gridDim.y;
    int Mv = jb.rows ? __ldg(jb.McPtr) : 0;

    __half* Bs  = smh;
    __half* As0 = smh + 128 * LDH;
    __half* As1 = As0 + 128 * LDH;
    uint32_t bsAddr   = (uint32_t)__cvta_generic_to_shared(Bs);
    uint32_t aAddr[2] = {(uint32_t)__cvta_generic_to_shared(As0),
                         (uint32_t)__cvta_generic_to_shared(As1)};

    int tid = threadIdx.x;
    int n0 = blockIdx.x * 128;

    {
        const __half* Wp = jb.W + (size_t)n0 * Dc;
#pragma unroll
        for (int it = 0; it < 4; it++) {
            int idx = tid + it * 512;
            int r = idx >> 4, ch = idx & 15;
            uint32_t d = bsAddr + (uint32_t)((r * LDH + ch * 8) * 2);
            asm volatile("cp.async.cg.shared.global [%0], [%1], 16;"
                         :: "r"(d), "l"(Wp + r * Dc + ch * 8));
        }
    }
    auto issueA = [&](int tile, int buf) {
#pragma unroll
        for (int it = 0; it < 4; it++) {
            int idx = tid + it * 512;
            int r = idx >> 4, ch = idx & 15;
            int gr = tile * 128 + r;
            const __half* Ap;
            if (jb.rows) {
                int cg = gr < Mv ? gr : Mv - 1;
                Ap = jb.A + (size_t)__ldg(&jb.rows[cg]) * Dc;
            } else {
                Ap = jb.A + (size_t)gr * Dc;
            }
            uint32_t d = aAddr[buf] + (uint32_t)((r * LDH + ch * 8) * 2);
            asm volatile("cp.async.cg.shared.global [%0], [%1], 16;"
                         :: "r"(d), "l"(Ap + ch * 8));
        }
    };
    issueA(t, 0);
    asm volatile("cp.async.commit_group;" ::: "memory");
    asm volatile("cp.async.wait_group 0;" ::: "memory");
    __syncthreads();

    int lane = tid & 31, wid = tid >> 5;
    int wm = (wid & 3) * 32, wn = (wid >> 2) * 32;
    int gid = lane >> 2, tig = lane & 3;

    uint32_t aoff[2], boff[2];
#pragma unroll
    for (int mt = 0; mt < 2; mt++)
        aoff[mt] = (uint32_t)(((wm + mt * 16 + (lane & 15)) * LDH + (lane >> 4) * 8) * 2);
#pragma unroll
    for (int p = 0; p < 2; p++)
        boff[p] = bsAddr + (uint32_t)(((wn + p * 16 + ((lane >> 4) << 3) + (lane & 7)) * LDH
                                      + ((lane >> 3) & 1) * 8) * 2);

#define LDFRAG(st, ks) do { \
    uint32_t kb = (uint32_t)((ks) * 32); \
    _Pragma("unroll") \
    for (int mt = 0; mt < 2; mt++) \
        asm volatile("ldmatrix.sync.aligned.m8n8.x4.shared.b16 {%0,%1,%2,%3}, [%4];" \
            : "=r"(af[st][mt][0]), "=r"(af[st][mt][1]), "=r"(af[st][mt][2]), "=r"(af[st][mt][3]) \
            : "r"(aCur + aoff[mt] + kb)); \
    _Pragma("unroll") \
    for (int p = 0; p < 2; p++) \
        asm volatile("ldmatrix.sync.aligned.m8n8.x4.shared.b16 {%0,%1,%2,%3}, [%4];" \
            : "=r"(bf[st][p][0]), "=r"(bf[st][p][1]), "=r"(bf[st][p][2]), "=r"(bf[st][p][3]) \
            : "r"(boff[p] + kb)); \
} while (0)

    int buf = 0;
    for (;;) {
        int tn = t + GY;
        if (tn < tiles) {
            issueA(tn, buf ^ 1);
            asm volatile("cp.async.commit_group;" ::: "memory");
        }
        uint32_t aCur = aAddr[buf];
        float acc[2][4][4];
#pragma unroll
        for (int mt = 0; mt < 2; mt++)
#pragma unroll
            for (int nt = 0; nt < 4; nt++)
#pragma unroll
                for (int q = 0; q < 4; q++) acc[mt][nt][q] = 0.f;

        uint32_t af[2][2][4], bf[2][2][4];
        LDFRAG(0, 0);
#pragma unroll
        for (int ks = 0; ks < 8; ks++) {
            int cu = ks & 1;
            if (ks < 7) LDFRAG(cu ^ 1, ks + 1);
#pragma unroll
            for (int mt = 0; mt < 2; mt++)
#pragma unroll
                for (int nt = 0; nt < 4; nt++) {
                    int p = nt >> 1, s = (nt & 1) * 2;
                    mma_f16(acc[mt][nt], af[cu][mt], bf[cu][p][s], bf[cu][p][s + 1]);
                }
        }
        int tm0 = t * 128;
#pragma unroll
        for (int mt = 0; mt < 2; mt++) {
            int r0 = tm0 + wm + mt * 16 + gid;
#pragma unroll
            for (int nt = 0; nt < 4; nt++) {
                int col = n0 + wn + nt * 8 + tig * 2;
                float2 bv = *(const float2*)&jb.bias[col];
                __half2 h0 = __floats2half2_rn(acc[mt][nt][0] + bv.x, acc[mt][nt][1] + bv.y);
                __half2 h1 = __floats2half2_rn(acc[mt][nt][2] + bv.x, acc[mt][nt][3] + bv.y);
                __stcs((unsigned int*)&jb.out[(size_t)r0 * HCc + col], *(unsigned int*)&h0);
                __stcs((unsigned int*)&jb.out[(size_t)(r0 + 8) * HCc + col], *(unsigned int*)&h1);
            }
        }
        if (tn >= tiles) break;
        asm volatile("cp.async.wait_group 0;" ::: "memory");
        __syncthreads();
        t = tn; buf ^= 1;
    }
#undef LDFRAG
}

// ---------------- misc ----------------
__global__ void k_zero4(float4* __restrict__ p, int n4) {
    int i = blockIdx.x * blockDim.x + threadIdx.x;
    if (i < n4) p[i] = make_float4(0.f, 0.f, 0.f, 0.f);
}
__global__ void k_embed(const int* __restrict__ idx, const float4* __restrict__ emb,
                        __half2* __restrict__ out, int n4) {
    int i = blockIdx.x * blockDim.x + threadIdx.x;
    if (i < n4) {
        float4 v = emb[idx[i >> 5] * 32 + (i & 31)];
        out[2 * i]     = __floats2half2_rn(v.x, v.y);
        out[2 * i + 1] = __floats2half2_rn(v.z, v.w);
    }
}

// ---------------- fused score+exp+denom over precomputed active edges ----------------
struct ScoreB {
    const int* aes[3]; const int* aer[3]; const int* aep[3]; const int* na;
    const __half* xl[3]; const __half* xr[3];
    const float* att[3];
    float* sc[3]; float* den[3];
};
__global__ void k_scorep(ScoreB P) {
    int z = blockIdx.z;
    int e = blockIdx.x * (blockDim.x >> 5) + (threadIdx.x >> 5);
    int lane = threadIdx.x & 31;
    if (e >= __ldg(&P.na[z])) return;
    int s   = P.aes[z][e];
    int rk  = P.aer[z][e];
    int pos = P.aep[z][e];
    const __half2* xls = (const __half2*)P.xl[z] + (size_t)s * 256;
    const __half2* xrd = (const __half2*)P.xr[z] + (size_t)rk * 256;
    const float* att = P.att[z];
    float part[4] = {0.f, 0.f, 0.f, 0.f};
#pragma unroll
    for (int h = 0; h < 4; h++)
#pragma unroll
        for (int k = 0; k < 2; k++) {
            int idx = h * 64 + k * 32 + lane;
            float2 a2 = __half22float2(xls[idx]);
            float2 b2 = __half22float2(xrd[idx]);
            float vx = a2.x + b2.x, vy = a2.y + b2.y;
            vx = vx > 0.f ? vx : SLOPEc * vx;
            vy = vy > 0.f ? vy : SLOPEc * vy;
            float2 at = *(const float2*)&att[2 * idx];
            part[h] += vx * at.x + vy * at.y;
        }
#pragma unroll
    for (int h = 0; h < 4; h++) {
        float v = part[h];
#pragma unroll
        for (int off = 16; off; off >>= 1) v += __shfl_down_sync(0xffffffffu, v, off);
        if (lane == 0) {
            float p = __expf(v);
            P.sc[z][pos * 4 + h] = p;
            atomicAdd(&P.den[z][rk * 4 + h], p);
        }
    }
}

// ---------------- CSR gather aggregation (1 warp per dst) + bias + relu -> cell ----------------
// Also resets den[rk] to 0 for the next layer (safe: one warp owns each dst).
struct AggB {
    const int* rs[3]; const int* csrc[3];
    const __half* xl[3];
    const float* sc[3]; float* den[3];
    const int* rank[3];
    const float* cb;
    __half* cell;
};
__global__ __launch_bounds__(256)
void k_aggr_g(AggB P) {
    int wid = threadIdx.x >> 5, lane = threadIdx.x & 31;
    int d = blockIdx.x * 8 + wid;
    float tot[4] = {0.f, 0.f, 0.f, 0.f};
#pragma unroll
    for (int r = 0; r < 3; r++) {
        int beg = P.rs[r][d], end = P.rs[r][d + 1];
        if (beg >= end) continue;
        const __half2* xlp = (const __half2*)P.xl[r];
        if (end - beg == 1) {
            const __half2* xls = xlp + (size_t)P.csrc[r][beg] * 256;
#pragma unroll
            for (int h = 0; h < 4; h++) {
                float2 a0 = __half22float2(xls[h * 64 + lane]);
                float2 a1 = __half22float2(xls[h * 64 + 32 + lane]);
                tot[0] += 0.25f * a0.x; tot[1] += 0.25f * a0.y;
                tot[2] += 0.25f * a1.x; tot[3] += 0.25f * a1.y;
            }
        } else {
            int rk = P.rank[r][d];
            float* denp = P.den[r] + rk * 4;
            float rc[4];
#pragma unroll
            for (int h = 0; h < 4; h++) rc[h] = 0.25f / (denp[h] + 1e-16f);
            if (lane < 4) denp[lane] = 0.f;   // reset for next layer (sole owner)
            const float* scp = P.sc[r];
            for (int e = beg; e < end; e++) {
                const __half2* xls = xlp + (size_t)P.csrc[r][e] * 256;
                float al[4];
#pragma unroll
                for (int h = 0; h < 4; h++) al[h] = scp[e * 4 + h] * rc[h];
#pragma unroll
                for (int h = 0; h < 4; h++) {
                    float2 a0 = __half22float2(xls[h * 64 + lane]);
                    float2 a1 = __half22float2(xls[h * 64 + 32 + lane]);
                    tot[0] += al[h] * a0.x; tot[1] += al[h] * a0.y;
                    tot[2] += al[h] * a1.x; tot[3] += al[h] * a1.y;
                }
            }
        }
    }
    int c0 = 2 * lane, c2 = 64 + 2 * lane;
    const float* cb = P.cb;
    float b0 = cb[c0] + cb[128 + c0] + cb[256 + c0];
    float b1 = cb[c0 + 1] + cb[128 + c0 + 1] + cb[256 + c0 + 1];
    float b2 = cb[c2] + cb[128 + c2] + cb[256 + c2];
    float b3 = cb[c2 + 1] + cb[128 + c2 + 1] + cb[256 + c2 + 1];
    __half2* cp = (__half2*)P.cell + (size_t)d * 64;
    cp[lane]      = __floats2half2_rn(fmaxf(tot[0] + b0, 0.f), fmaxf(tot[1] + b1, 0.f));
    cp[32 + lane] = __floats2half2_rn(fmaxf(tot[2] + b2, 0.f), fmaxf(tot[3] + b3, 0.f));
}

// ---------------- pooling ----------------
__global__ void k_pool(const __half* __restrict__ cell, const int* __restrict__ batch,
                       float* __restrict__ sums, float* __restrict__ cnts) {
    __shared__ __half sc[64 * 128];
    __shared__ int sb[64];
    int g = blockIdx.x;
    int tid = threadIdx.x;  // 128
    const int4* src = (const int4*)(cell + (size_t)g * 64 * 128);
    int4* dst = (int4*)sc;
#pragma unroll
    for (int i = 0; i < 8; i++) dst[tid + i * 128] = src[tid + i * 128];
    if (tid < 64) sb[tid] = batch[g * 64 + tid];
    __syncthreads();
    float a = 0.f, c = 0.f;
#pragma unroll 4
    for (int r = 0; r < 64; r++) {
        a += __half2float(sc[r * 128 + tid]);
        c += 1.f;
        if (r == 63 || sb[r + 1] != sb[r]) {
            atomicAdd(&sums[(size_t)sb[r] * Dc + tid], a);
            if (tid == 0) atomicAdd(&cnts[sb[r]], c);
            a = 0.f; c = 0.f;
        }
    }
}

// ---------------- heads ----------------
__global__ void k_head(const float* __restrict__ sums, const float* __restrict__ cnts,
                       const float* __restrict__ fc1W, const float* __restrict__ fc1b,
                       const float* __restrict__ polW, const float* __restrict__ polb,
                       const float* __restrict__ valW, const float* __restrict__ valb,
                       float* __restrict__ out_policy, float* __restrict__ out_value) {
    int b = blockIdx.x;
    int t = threadIdx.x;  // 64
    __shared__ float pooled[128];
    __shared__ float hsh[64];
    float cnt = fmaxf(cnts[b], 1.f);
    pooled[t]      = sums[b * Dc + t] / cnt;
    pooled[t + 64] = sums[b * Dc + 64 + t] / cnt;
    __syncthreads();
    float a = fc1b[t];
#pragma unroll 4
    for (int d = 0; d < 128; d++) a += pooled[d] * fc1W[d * 64 + t];
    hsh[t] = fmaxf(a, 0.f);
    __syncthreads();
    if (t < BWc) {
        float a2 = polb[t];
#pragma unroll 4
        for (int k = 0; k < 64; k++) a2 += hsh[k] * polW[k * BWc + t];
        out_policy[b * BWc + t] = a2;
    }
    if (t == 8) {
        float a2 = valb[0];
#pragma unroll 4
        for (int k = 0; k < 64; k++) a2 += hsh[k] * valW[k];
        out_value[b] = tanhf(a2);
    }
}

// ---------------- launch ----------------
extern "C" void kernel_launch(void* const* d_in, const int* in_sizes, int n_in,
                              void* d_out, int out_size) {
    const int* cell_x     = (const int*)d_in[0];
    const int* piece_x    = (const int*)d_in[1];
    const int* srcs[3]    = {(const int*)d_in[2], (const int*)d_in[4], (const int*)d_in[6]};
    const int* dsts[3]    = {(const int*)d_in[3], (const int*)d_in[5], (const int*)d_in[7]};
    const int  Es[3]      = {in_sizes[2], in_sizes[4], in_sizes[6]};
    const int* cell_batch = (const int*)d_in[8];
    const float* cell_emb  = (const float*)d_in[9];
    const float* piece_emb = (const float*)d_in[10];
    const float* Wl  = (const float*)d_in[11];
    const float* bl  = (const float*)d_in[12];
    const float* Wr  = (const float*)d_in[13];
    const float* br  = (const float*)d_in[14];
    const float* att = (const float*)d_in[15];
    const float* cb  = (const float*)d_in[16];
    const float* fc1W = (const float*)d_in[17];
    const float* fc1b = (const float*)d_in[18];
    const float* polW = (const float*)d_in[19];
    const float* polb = (const float*)d_in[20];
    const float* valW = (const float*)d_in[21];
    const float* valb = (const float*)d_in[22];

    const int NC = in_sizes[0];
    const int NP = in_sizes[1];

    float *p_sums, *p_cnts, *p_sc, *p_den;
    __half *p_cell, *p_piece, *p_wt;
    __half *p_xl[3], *p_xr[3];
    int *p_deg, *p_cur, *p_rs, *p_csrc, *p_rank, *p_list, *p_mc, *p_jt;
    int *p_aes, *p_aer, *p_aep, *p_na;
    cudaGetSymbolAddress((void**)&p_cell,  g_cell);
    cudaGetSymbolAddress((void**)&p_piece, g_piece);
    cudaGetSymbolAddress((void**)&p_xl[0], g_xl0);
    cudaGetSymbolAddress((void**)&p_xl[1], g_xl1);
    cudaGetSymbolAddress((void**)&p_xl[2], g_xl2);
    cudaGetSymbolAddress((void**)&p_xr[0], g_xr0);
    cudaGetSymbolAddress((void**)&p_xr[1], g_xr1);
    cudaGetSymbolAddress((void**)&p_xr[2], g_xr2);
    cudaGetSymbolAddress((void**)&p_sc,    g_sc);
    cudaGetSymbolAddress((void**)&p_den,   g_den);
    cudaGetSymbolAddress((void**)&p_sums,  g_sums);
    cudaGetSymbolAddress((void**)&p_cnts,  g_cnts);
    cudaGetSymbolAddress((void**)&p_wt,    g_wt);
    cudaGetSymbolAddress((void**)&p_deg,   g_deg);
    cudaGetSymbolAddress((void**)&p_cur,   g_cur);
    cudaGetSymbolAddress((void**)&p_rs,    g_rs);
    cudaGetSymbolAddress((void**)&p_csrc,  g_csrc);
    cudaGetSymbolAddress((void**)&p_rank,  g_rank);
    cudaGetSymbolAddress((void**)&p_list,  g_list);
    cudaGetSymbolAddress((void**)&p_mc,    g_mc);
    cudaGetSymbolAddress((void**)&p_jt,    g_jt);
    cudaGetSymbolAddress((void**)&p_aes,   g_aes);
    cudaGetSymbolAddress((void**)&p_aer,   g_aer);
    cudaGetSymbolAddress((void**)&p_aep,   g_aep);
    cudaGetSymbolAddress((void**)&p_na,    g_na);

    const int SMEM_GEMM = 3 * 128 * LDH * 2;
    cudaFuncSetAttribute(k_gemm, cudaFuncAttributeMaxDynamicSharedMemorySize, SMEM_GEMM);

    const int T = 256;
    const size_t MATSZ = (size_t)Dc * HCc;

    // ---- weight prep + embeddings ----
    k_wprep<<<dim3(16, 4, 12), dim3(32, 8)>>>(Wl, p_wt);
    k_wprep<<<dim3(16, 4, 12), dim3(32, 8)>>>(Wr, p_wt + 12 * MATSZ);
    k_embed<<<(NC * 32 + T - 1) / T, T>>>(cell_x, (const float4*)cell_emb, (__half2*)p_cell, NC * 32);
    k_embed<<<(NP * 32 + T - 1) / T, T>>>(piece_x, (const float4*)piece_emb, (__half2*)p_piece, NP * 32);

    // ---- degrees + CSR + compaction (edges static) ----
    DegB db;
    int Emax = 0;
    for (int r = 0; r < 3; r++) {
        db.dst[r] = dsts[r]; db.src[r] = srcs[r]; db.E[r] = Es[r];
        if (Es[r] > Emax) Emax = Es[r];
    }
    k_zero4<<<(3 * NCc / 4 + T - 1) / T, T>>>((float4*)p_deg, 3 * NCc / 4);
    k_zero4<<<(3 * NCc / 4 + T - 1) / T, T>>>((float4*)p_cur, 3 * NCc / 4);
    k_zero4<<<(3 * NCc * Hc / 4 + T - 1) / T, T>>>((float4*)p_den, 3 * NCc * Hc / 4);
    k_hist<<<dim3((Emax + T - 1) / T, 1, 3), T>>>(db, p_deg);
    k_jt_init<<<1, 1>>>(p_jt, p_na);
    k_scan_all<<<3, 1024>>>(p_deg, p_rs, p_rank, p_list, p_mc, p_jt);
    ScatB sbb;
    for (int r = 0; r < 3; r++) {
        sbb.dst[r] = dsts[r]; sbb.src[r] = srcs[r];
        sbb.deg[r]  = p_deg  + (size_t)r * NCc;
        sbb.rank[r] = p_rank + (size_t)r * NCc;
        sbb.rs[r]   = p_rs   + (size_t)r * (NCc + 1);
        sbb.cur[r]  = p_cur  + (size_t)r * NCc;
        sbb.csrc[r] = p_csrc + (size_t)r * EMAXc;
        sbb.aes[r]  = p_aes  + (size_t)r * EMAXc;
        sbb.aer[r]  = p_aer  + (size_t)r * EMAXc;
        sbb.aep[r]  = p_aep  + (size_t)r * EMAXc;
        sbb.E[r] = Es[r];
    }
    sbb.na = p_na;
    k_scatter<<<dim3((Emax + T - 1) / T, 1, 3), T>>>(sbb);

    // ---- layers ----
    for (int l = 0; l < Lc; l++) {
        GemmBatch gb;
        for (int z = 0; z < 6; z++) {
            int r = (z == 0 || z == 1) ? 0 : (z <= 3 ? 1 : 2);
            bool isL = (z == 0) || (z == 2) || (z == 4);
            int mat = l * 3 + r;
            gb.j[z].A        = (z == 0) ? p_piece : p_cell;
            gb.j[z].W        = p_wt + (isL ? mat : 12 + mat) * MATSZ;
            gb.j[z].bias     = (isL ? bl : br) + (size_t)mat * HCc;
            gb.j[z].out      = isL ? p_xl[r] : p_xr[r];
            gb.j[z].rows     = isL ? nullptr : (p_list + (size_t)r * NCc);
            gb.j[z].tilesPtr = p_jt + z;
            gb.j[z].McPtr    = isL ? nullptr : (p_mc + r);
        }
        k_gemm<<<dim3(4, 37, 6), 512, SMEM_GEMM>>>(gb);

        ScoreB eb;
        for (int r = 0; r < 3; r++) {
            eb.aes[r] = p_aes + (size_t)r * EMAXc;
            eb.aer[r] = p_aer + (size_t)r * EMAXc;
            eb.aep[r] = p_aep + (size_t)r * EMAXc;
            eb.xl[r] = p_xl[r]; eb.xr[r] = p_xr[r];
            eb.att[r] = att + (size_t)(l * 3 + r) * HCc;
            eb.sc[r]  = p_sc  + (size_t)r * EMAXc * Hc;
            eb.den[r] = p_den + (size_t)r * NCc * Hc;
        }
        eb.na = p_na;
        int wpb = T / 32;
        k_scorep<<<dim3((Emax + wpb - 1) / wpb, 1, 3), T>>>(eb);

        AggB ab;
        for (int r = 0; r < 3; r++) {
            ab.rs[r]   = p_rs   + (size_t)r * (NCc + 1);
            ab.csrc[r] = p_csrc + (size_t)r * EMAXc;
            ab.xl[r]   = p_xl[r];
            ab.sc[r]   = p_sc  + (size_t)r * EMAXc * Hc;
            ab.den[r]  = p_den + (size_t)r * NCc * Hc;
            ab.rank[r] = p_rank + (size_t)r * NCc;
        }
        ab.cb   = cb + (size_t)l * 3 * Cc;
        ab.cell = p_cell;
        k_aggr_g<<<NC / 8, 256>>>(ab);
    }

    // ---- pool + heads ----
    k_zero4<<<(Bc * 32 + T - 1) / T, T>>>((float4*)p_sums, Bc * 32);
    k_zero4<<<(Bc / 4 + T - 1) / T, T>>>((float4*)p_cnts, Bc / 4);
    k_pool<<<NC / 64, 128>>>(p_cell, cell_batch, p_sums, p_cnts);

    float* out = (float*)d_out;
    k_head<<<Bc, 64>>>(p_sums, p_cnts, fc1W, fc1b, polW, polb, valW, valb,
                       out, out + (size_t)Bc * BWc);
}

// round 15
// speedup vs baseline: 1.0980x; 1.0138x over previous
#include <cuda_runtime.h>
#include <cuda_fp16.h>
#include <cstdint>
#include <math.h>

// Problem constants
#define NCc 65536
#define NPc 32768
#define Dc  128
#define Hc  4
#define Cc  128
#define HCc 512
#define Bc  1024
#define Lc  4
#define BWc 7
#define SLOPEc 0.2f
#define EMAXc 65536

// ---------------- scratch (device globals) ----------------
__device__ __half g_cell [NCc * Dc];
__device__ __half g_piece[NPc * Dc];
__device__ __half g_xl0  [NPc * HCc];
__device__ __half g_xl1  [NCc * HCc];
__device__ __half g_xl2  [NCc * HCc];
__device__ __half g_xr0  [NCc * HCc];   // compact rows (deg>=2 dsts)
__device__ __half g_xr1  [NCc * HCc];
__device__ __half g_xr2  [NCc * HCc];
__device__ float  g_sc   [3][EMAXc * Hc];   // p values, CSR order
__device__ float  g_den  [3][NCc * Hc];     // compact by rank
__device__ float  g_sums [Bc * Dc];
__device__ float  g_cnts [Bc];
__device__ __half g_wt   [24 * HCc * Dc];
// CSR / degree / compaction
__device__ int    g_deg  [3][NCc];
__device__ int    g_cur  [3][NCc];
__device__ int    g_rs   [3][NCc + 1];
__device__ int    g_csrc [3][EMAXc];
__device__ int    g_rank [3][NCc];
__device__ int    g_list [3][NCc];
__device__ int    g_mc   [3];
__device__ int    g_jt   [6];
// active-edge compaction (deg[dst]>=2 edges only)
__device__ int    g_aes  [3][EMAXc];   // src
__device__ int    g_aer  [3][EMAXc];   // dst rank
__device__ int    g_aep  [3][EMAXc];   // CSR pos
__device__ int    g_na   [3];          // counts

// ---------------- helpers ----------------
__device__ __forceinline__ void mma_f16(float* c, const uint32_t* a, uint32_t b0, uint32_t b1) {
    asm volatile(
        "mma.sync.aligned.m16n8k16.row.col.f32.f16.f16.f32 "
        "{%0,%1,%2,%3}, {%4,%5,%6,%7}, {%8,%9}, {%0,%1,%2,%3};"
        : "+f"(c[0]), "+f"(c[1]), "+f"(c[2]), "+f"(c[3])
        : "r"(a[0]), "r"(a[1]), "r"(a[2]), "r"(a[3]), "r"(b0), "r"(b1));
}

// ---------------- weight prep ----------------
__global__ void k_wprep(const float* __restrict__ W, __half* __restrict__ WT) {
    __shared__ float t[32][33];
    int mat = blockIdx.z;
    int n0 = blockIdx.x * 32, k0 = blockIdx.y * 32;
    int x = threadIdx.x, y = threadIdx.y;
    const float* w  = W  + (size_t)mat * Dc * HCc;
    __half*      wt = WT + (size_t)mat * Dc * HCc;
#pragma unroll
    for (int j = 0; j < 4; j++)
        t[y + 8 * j][x] = w[(size_t)(k0 + y + 8 * j) * HCc + n0 + x];
    __syncthreads();
#pragma unroll
    for (int j = 0; j < 4; j++)
        wt[(size_t)(n0 + y + 8 * j) * Dc + k0 + x] = __float2half_rn(t[x][y + 8 * j]);
}

// ---------------- degree + CSR + compaction ----------------
struct DegB { const int* dst[3]; const int* src[3]; int E[3]; };
__global__ void k_hist(DegB D, int* __restrict__ deg) {
    int z = blockIdx.z;
    int i = blockIdx.x * blockDim.x + threadIdx.x;
    if (i < D.E[z]) atomicAdd(&deg[z * NCc + D.dst[z][i]], 1);
}
__global__ void k_jt_init(int* __restrict__ jt, int* __restrict__ na) {
    jt[0] = NPc / 64; jt[2] = NCc / 64; jt[4] = NCc / 64;
    na[0] = na[1] = na[2] = 0;
}
__global__ void k_scan_all(const int* __restrict__ deg, int* __restrict__ rs,
                           int* __restrict__ rank, int* __restrict__ list,
                           int* __restrict__ mc, int* __restrict__ jt) {
    int z = blockIdx.x;
    const int* dg = deg + z * NCc;
    int* rsz = rs + z * (NCc + 1);
    int* rk  = rank + z * NCc;
    int* ls  = list + z * NCc;
    int t = threadIdx.x;            // 1024
    const int chunk = NCc >> 10;    // 64
    int base = t * chunk;
    int se = 0, s2 = 0;
#pragma unroll 4
    for (int i = 0; i < chunk; i++) {
        int v = dg[base + i];
        se += v; s2 += (v >= 2);
    }
    __shared__ int sme[1024], sm2[1024];
    sme[t] = se; sm2[t] = s2;
    __syncthreads();
    for (int off = 1; off < 1024; off <<= 1) {
        int ve = (t >= off) ? sme[t - off] : 0;
        int v2 = (t >= off) ? sm2[t - off] : 0;
        __syncthreads();
        sme[t] += ve; sm2[t] += v2;
        __syncthreads();
    }
    int rune = sme[t] - se, run2 = sm2[t] - s2;
    for (int i = 0; i < chunk; i++) {
        int g = base + i;
        int v = dg[g];
        rsz[g] = rune; rune += v;
        if (v >= 2) { rk[g] = run2; ls[run2] = g; run2++; }
        else rk[g] = -1;
    }
    if (t == 1023) {
        rsz[NCc] = rune;
        mc[z] = run2;
        jt[2 * z + 1] = (run2 + 63) / 64;
    }
}
struct ScatB {
    const int* dst[3]; const int* src[3];
    const int* deg[3]; const int* rank[3];
    int* rs[3]; int* cur[3]; int* csrc[3];
    int* aes[3]; int* aer[3]; int* aep[3]; int* na;
    int E[3];
};
__global__ void k_scatter(ScatB C) {
    int z = blockIdx.z;
    int i = blockIdx.x * blockDim.x + threadIdx.x;
    if (i < C.E[z]) {
        int d = C.dst[z][i];
        int s = C.src[z][i];
        int pos = C.rs[z][d] + atomicAdd(&C.cur[z][d], 1);
        C.csrc[z][pos] = s;
        if (C.deg[z][d] >= 2) {
            int a = atomicAdd(&C.na[z], 1);
            C.aes[z][a] = s;
            C.aer[z][a] = C.rank[z][d];
            C.aep[z][a] = pos;
        }
    }
}

// ---------------- batched strip-mined fp16 GEMM (BM=64, 256 thr, 2 CTA/SM) ----------------
struct GemmJob {
    const __half* A; const __half* W; const float* bias; __half* out;
    const int* rows; const int* tilesPtr; const int* McPtr;
};
struct GemmBatch { GemmJob j[6]; };

#define LDH 136
__global__ __launch_bounds__(256, 2)
void k_gemm(GemmBatch P) {
    extern __shared__ __half smh[];
    const GemmJob jb = P.j[blockIdx.z];
    int tiles = __ldg(jb.tilesPtr);
    int t = blockIdx.y;
    if (t >= tiles) return;
    const int GY = gridDim.y;
    int Mv = jb.rows ? __ldg(jb.McPtr) : 0;

    __half* Bs  = smh;                       // 128 x LDH
    __half* As0 = smh + 128 * LDH;           // 64 x LDH
    __half* As1 = As0 + 64 * LDH;
    uint32_t bsAddr   = (uint32_t)__cvta_generic_to_shared(Bs);
    uint32_t aAddr[2] = {(uint32_t)__cvta_generic_to_shared(As0),
                         (uint32_t)__cvta_generic_to_shared(As1)};

    int tid = threadIdx.x;
    int n0 = blockIdx.x * 128;

    {
        const __half* Wp = jb.W + (size_t)n0 * Dc;
#pragma unroll
        for (int it = 0; it < 8; it++) {
            int idx = tid + it * 256;
            int r = idx >> 4, ch = idx & 15;
            uint32_t d = bsAddr + (uint32_t)((r * LDH + ch * 8) * 2);
            asm volatile("cp.async.cg.shared.global [%0], [%1], 16;"
                         :: "r"(d), "l"(Wp + r * Dc + ch * 8));
        }
    }
    auto issueA = [&](int tile, int buf) {
#pragma unroll
        for (int it = 0; it < 4; it++) {
            int idx = tid + it * 256;
            int r = idx >> 4, ch = idx & 15;
            int gr = tile * 64 + r;
            const __half* Ap;
            if (jb.rows) {
                int cg = gr < Mv ? gr : Mv - 1;
                Ap = jb.A + (size_t)__ldg(&jb.rows[cg]) * Dc;
            } else {
                Ap = jb.A + (size_t)gr * Dc;
            }
            uint32_t d = aAddr[buf] + (uint32_t)((r * LDH + ch * 8) * 2);
            asm volatile("cp.async.cg.shared.global [%0], [%1], 16;"
                         :: "r"(d), "l"(Ap + ch * 8));
        }
    };
    issueA(t, 0);
    asm volatile("cp.async.commit_group;" ::: "memory");
    asm volatile("cp.async.wait_group 0;" ::: "memory");
    __syncthreads();

    int lane = tid & 31, wid = tid >> 5;
    int wm = (wid & 1) * 32, wn = (wid >> 1) * 32;   // 2x4 warps, warp tile 32x32
    int gid = lane >> 2, tig = lane & 3;

    uint32_t aoff[2], boff[2];
#pragma unroll
    for (int mt = 0; mt < 2; mt++)
        aoff[mt] = (uint32_t)(((wm + mt * 16 + (lane & 15)) * LDH + (lane >> 4) * 8) * 2);
#pragma unroll
    for (int p = 0; p < 2; p++)
        boff[p] = bsAddr + (uint32_t)(((wn + p * 16 + ((lane >> 4) << 3) + (lane & 7)) * LDH
                                      + ((lane >> 3) & 1) * 8) * 2);

#define LDFRAG(st, ks) do { \
    uint32_t kb = (uint32_t)((ks) * 32); \
    _Pragma("unroll") \
    for (int mt = 0; mt < 2; mt++) \
        asm volatile("ldmatrix.sync.aligned.m8n8.x4.shared.b16 {%0,%1,%2,%3}, [%4];" \
            : "=r"(af[st][mt][0]), "=r"(af[st][mt][1]), "=r"(af[st][mt][2]), "=r"(af[st][mt][3]) \
            : "r"(aCur + aoff[mt] + kb)); \
    _Pragma("unroll") \
    for (int p = 0; p < 2; p++) \
        asm volatile("ldmatrix.sync.aligned.m8n8.x4.shared.b16 {%0,%1,%2,%3}, [%4];" \
            : "=r"(bf[st][p][0]), "=r"(bf[st][p][1]), "=r"(bf[st][p][2]), "=r"(bf[st][p][3]) \
            : "r"(boff[p] + kb)); \
} while (0)

    int buf = 0;
    for (;;) {
        int tn = t + GY;
        if (tn < tiles) {
            issueA(tn, buf ^ 1);
            asm volatile("cp.async.commit_group;" ::: "memory");
        }
        uint32_t aCur = aAddr[buf];
        float acc[2][4][4];
#pragma unroll
        for (int mt = 0; mt < 2; mt++)
#pragma unroll
            for (int nt = 0; nt < 4; nt++)
#pragma unroll
                for (int q = 0; q < 4; q++) acc[mt][nt][q] = 0.f;

        uint32_t af[2][2][4], bf[2][2][4];
        LDFRAG(0, 0);
#pragma unroll
        for (int ks = 0; ks < 8; ks++) {
            int cu = ks & 1;
            if (ks < 7) LDFRAG(cu ^ 1, ks + 1);
#pragma unroll
            for (int mt = 0; mt < 2; mt++)
#pragma unroll
                for (int nt = 0; nt < 4; nt++) {
                    int p = nt >> 1, s = (nt & 1) * 2;
                    mma_f16(acc[mt][nt], af[cu][mt], bf[cu][p][s], bf[cu][p][s + 1]);
                }
        }
        int tm0 = t * 64;
#pragma unroll
        for (int mt = 0; mt < 2; mt++) {
            int r0 = tm0 + wm + mt * 16 + gid;
#pragma unroll
            for (int nt = 0; nt < 4; nt++) {
                int col = n0 + wn + nt * 8 + tig * 2;
                float2 bv = *(const float2*)&jb.bias[col];
                __half2 h0 = __floats2half2_rn(acc[mt][nt][0] + bv.x, acc[mt][nt][1] + bv.y);
                __half2 h1 = __floats2half2_rn(acc[mt][nt][2] + bv.x, acc[mt][nt][3] + bv.y);
                __stcs((unsigned int*)&jb.out[(size_t)r0 * HCc + col], *(unsigned int*)&h0);
                __stcs((unsigned int*)&jb.out[(size_t)(r0 + 8) * HCc + col], *(unsigned int*)&h1);
            }
        }
        if (tn >= tiles) break;
        asm volatile("cp.async.wait_group 0;" ::: "memory");
        __syncthreads();
        t = tn; buf ^= 1;
    }
#undef LDFRAG
}

// ---------------- misc ----------------
__global__ void k_zero4(float4* __restrict__ p, int n4) {
    int i = blockIdx.x * blockDim.x + threadIdx.x;
    if (i < n4) p[i] = make_float4(0.f, 0.f, 0.f, 0.f);
}
__global__ void k_embed(const int* __restrict__ idx, const float4* __restrict__ emb,
                        __half2* __restrict__ out, int n4) {
    int i = blockIdx.x * blockDim.x + threadIdx.x;
    if (i < n4) {
        float4 v = emb[idx[i >> 5] * 32 + (i & 31)];
        out[2 * i]     = __floats2half2_rn(v.x, v.y);
        out[2 * i + 1] = __floats2half2_rn(v.z, v.w);
    }
}

// ---------------- fused score+exp+denom over precomputed active edges ----------------
struct ScoreB {
    const int* aes[3]; const int* aer[3]; const int* aep[3]; const int* na;
    const __half* xl[3]; const __half* xr[3];
    const float* att[3];
    float* sc[3]; float* den[3];
};
__global__ void k_scorep(ScoreB P) {
    int z = blockIdx.z;
    int e = blockIdx.x * (blockDim.x >> 5) + (threadIdx.x >> 5);
    int lane = threadIdx.x & 31;
    if (e >= __ldg(&P.na[z])) return;
    int s   = P.aes[z][e];
    int rk  = P.aer[z][e];
    int pos = P.aep[z][e];
    const __half2* xls = (const __half2*)P.xl[z] + (size_t)s * 256;
    const __half2* xrd = (const __half2*)P.xr[z] + (size_t)rk * 256;
    const float* att = P.att[z];
    float part[4] = {0.f, 0.f, 0.f, 0.f};
#pragma unroll
    for (int h = 0; h < 4; h++)
#pragma unroll
        for (int k = 0; k < 2; k++) {
            int idx = h * 64 + k * 32 + lane;
            float2 a2 = __half22float2(xls[idx]);
            float2 b2 = __half22float2(xrd[idx]);
            float vx = a2.x + b2.x, vy = a2.y + b2.y;
            vx = vx > 0.f ? vx : SLOPEc * vx;
            vy = vy > 0.f ? vy : SLOPEc * vy;
            float2 at = *(const float2*)&att[2 * idx];
            part[h] += vx * at.x + vy * at.y;
        }
#pragma unroll
    for (int h = 0; h < 4; h++) {
        float v = part[h];
#pragma unroll
        for (int off = 16; off; off >>= 1) v += __shfl_down_sync(0xffffffffu, v, off);
        if (lane == 0) {
            float p = __expf(v);
            P.sc[z][pos * 4 + h] = p;
            atomicAdd(&P.den[z][rk * 4 + h], p);
        }
    }
}

// ---------------- CSR gather aggregation (1 warp per dst) + bias + relu -> cell ----------------
struct AggB {
    const int* rs[3]; const int* csrc[3];
    const __half* xl[3];
    const float* sc[3]; float* den[3];
    const int* rank[3];
    const float* cb;
    __half* cell;
};
__global__ __launch_bounds__(256)
void k_aggr_g(AggB P) {
    int wid = threadIdx.x >> 5, lane = threadIdx.x & 31;
    int d = blockIdx.x * 8 + wid;
    float tot[4] = {0.f, 0.f, 0.f, 0.f};
#pragma unroll
    for (int r = 0; r < 3; r++) {
        int beg = P.rs[r][d], end = P.rs[r][d + 1];
        if (beg >= end) continue;
        const __half2* xlp = (const __half2*)P.xl[r];
        if (end - beg == 1) {
            const __half2* xls = xlp + (size_t)P.csrc[r][beg] * 256;
#pragma unroll
            for (int h = 0; h < 4; h++) {
                float2 a0 = __half22float2(xls[h * 64 + lane]);
                float2 a1 = __half22float2(xls[h * 64 + 32 + lane]);
                tot[0] += 0.25f * a0.x; tot[1] += 0.25f * a0.y;
                tot[2] += 0.25f * a1.x; tot[3] += 0.25f * a1.y;
            }
        } else {
            int rk = P.rank[r][d];
            float* denp = P.den[r] + rk * 4;
            float rc[4];
#pragma unroll
            for (int h = 0; h < 4; h++) rc[h] = 0.25f / (denp[h] + 1e-16f);
            if (lane < 4) denp[lane] = 0.f;   // reset for next layer (sole owner)
            const float* scp = P.sc[r];
            for (int e = beg; e < end; e++) {
                const __half2* xls = xlp + (size_t)P.csrc[r][e] * 256;
                float al[4];
#pragma unroll
                for (int h = 0; h < 4; h++) al[h] = scp[e * 4 + h] * rc[h];
#pragma unroll
                for (int h = 0; h < 4; h++) {
                    float2 a0 = __half22float2(xls[h * 64 + lane]);
                    float2 a1 = __half22float2(xls[h * 64 + 32 + lane]);
                    tot[0] += al[h] * a0.x; tot[1] += al[h] * a0.y;
                    tot[2] += al[h] * a1.x; tot[3] += al[h] * a1.y;
                }
            }
        }
    }
    int c0 = 2 * lane, c2 = 64 + 2 * lane;
    const float* cb = P.cb;
    float b0 = cb[c0] + cb[128 + c0] + cb[256 + c0];
    float b1 = cb[c0 + 1] + cb[128 + c0 + 1] + cb[256 + c0 + 1];
    float b2 = cb[c2] + cb[128 + c2] + cb[256 + c2];
    float b3 = cb[c2 + 1] + cb[128 + c2 + 1] + cb[256 + c2 + 1];
    __half2* cp = (__half2*)P.cell + (size_t)d * 64;
    cp[lane]      = __floats2half2_rn(fmaxf(tot[0] + b0, 0.f), fmaxf(tot[1] + b1, 0.f));
    cp[32 + lane] = __floats2half2_rn(fmaxf(tot[2] + b2, 0.f), fmaxf(tot[3] + b3, 0.f));
}

// ---------------- pooling ----------------
__global__ void k_pool(const __half* __restrict__ cell, const int* __restrict__ batch,
                       float* __restrict__ sums, float* __restrict__ cnts) {
    __shared__ __half sc[64 * 128];
    __shared__ int sb[64];
    int g = blockIdx.x;
    int tid = threadIdx.x;  // 128
    const int4* src = (const int4*)(cell + (size_t)g * 64 * 128);
    int4* dst = (int4*)sc;
#pragma unroll
    for (int i = 0; i < 8; i++) dst[tid + i * 128] = src[tid + i * 128];
    if (tid < 64) sb[tid] = batch[g * 64 + tid];
    __syncthreads();
    float a = 0.f, c = 0.f;
#pragma unroll 4
    for (int r = 0; r < 64; r++) {
        a += __half2float(sc[r * 128 + tid]);
        c += 1.f;
        if (r == 63 || sb[r + 1] != sb[r]) {
            atomicAdd(&sums[(size_t)sb[r] * Dc + tid], a);
            if (tid == 0) atomicAdd(&cnts[sb[r]], c);
            a = 0.f; c = 0.f;
        }
    }
}

// ---------------- heads ----------------
__global__ void k_head(const float* __restrict__ sums, const float* __restrict__ cnts,
                       const float* __restrict__ fc1W, const float* __restrict__ fc1b,
                       const float* __restrict__ polW, const float* __restrict__ polb,
                       const float* __restrict__ valW, const float* __restrict__ valb,
                       float* __restrict__ out_policy, float* __restrict__ out_value) {
    int b = blockIdx.x;
    int t = threadIdx.x;  // 64
    __shared__ float pooled[128];
    __shared__ float hsh[64];
    float cnt = fmaxf(cnts[b], 1.f);
    pooled[t]      = sums[b * Dc + t] / cnt;
    pooled[t + 64] = sums[b * Dc + 64 + t] / cnt;
    __syncthreads();
    float a = fc1b[t];
#pragma unroll 4
    for (int d = 0; d < 128; d++) a += pooled[d] * fc1W[d * 64 + t];
    hsh[t] = fmaxf(a, 0.f);
    __syncthreads();
    if (t < BWc) {
        float a2 = polb[t];
#pragma unroll 4
        for (int k = 0; k < 64; k++) a2 += hsh[k] * polW[k * BWc + t];
        out_policy[b * BWc + t] = a2;
    }
    if (t == 8) {
        float a2 = valb[0];
#pragma unroll 4
        for (int k = 0; k < 64; k++) a2 += hsh[k] * valW[k];
        out_value[b] = tanhf(a2);
    }
}

// ---------------- launch ----------------
extern "C" void kernel_launch(void* const* d_in, const int* in_sizes, int n_in,
                              void* d_out, int out_size) {
    const int* cell_x     = (const int*)d_in[0];
    const int* piece_x    = (const int*)d_in[1];
    const int* srcs[3]    = {(const int*)d_in[2], (const int*)d_in[4], (const int*)d_in[6]};
    const int* dsts[3]    = {(const int*)d_in[3], (const int*)d_in[5], (const int*)d_in[7]};
    const int  Es[3]      = {in_sizes[2], in_sizes[4], in_sizes[6]};
    const int* cell_batch = (const int*)d_in[8];
    const float* cell_emb  = (const float*)d_in[9];
    const float* piece_emb = (const float*)d_in[10];
    const float* Wl  = (const float*)d_in[11];
    const float* bl  = (const float*)d_in[12];
    const float* Wr  = (const float*)d_in[13];
    const float* br  = (const float*)d_in[14];
    const float* att = (const float*)d_in[15];
    const float* cb  = (const float*)d_in[16];
    const float* fc1W = (const float*)d_in[17];
    const float* fc1b = (const float*)d_in[18];
    const float* polW = (const float*)d_in[19];
    const float* polb = (const float*)d_in[20];
    const float* valW = (const float*)d_in[21];
    const float* valb = (const float*)d_in[22];

    const int NC = in_sizes[0];
    const int NP = in_sizes[1];

    float *p_sums, *p_cnts, *p_sc, *p_den;
    __half *p_cell, *p_piece, *p_wt;
    __half *p_xl[3], *p_xr[3];
    int *p_deg, *p_cur, *p_rs, *p_csrc, *p_rank, *p_list, *p_mc, *p_jt;
    int *p_aes, *p_aer, *p_aep, *p_na;
    cudaGetSymbolAddress((void**)&p_cell,  g_cell);
    cudaGetSymbolAddress((void**)&p_piece, g_piece);
    cudaGetSymbolAddress((void**)&p_xl[0], g_xl0);
    cudaGetSymbolAddress((void**)&p_xl[1], g_xl1);
    cudaGetSymbolAddress((void**)&p_xl[2], g_xl2);
    cudaGetSymbolAddress((void**)&p_xr[0], g_xr0);
    cudaGetSymbolAddress((void**)&p_xr[1], g_xr1);
    cudaGetSymbolAddress((void**)&p_xr[2], g_xr2);
    cudaGetSymbolAddress((void**)&p_sc,    g_sc);
    cudaGetSymbolAddress((void**)&p_den,   g_den);
    cudaGetSymbolAddress((void**)&p_sums,  g_sums);
    cudaGetSymbolAddress((void**)&p_cnts,  g_cnts);
    cudaGetSymbolAddress((void**)&p_wt,    g_wt);
    cudaGetSymbolAddress((void**)&p_deg,   g_deg);
    cudaGetSymbolAddress((void**)&p_cur,   g_cur);
    cudaGetSymbolAddress((void**)&p_rs,    g_rs);
    cudaGetSymbolAddress((void**)&p_csrc,  g_csrc);
    cudaGetSymbolAddress((void**)&p_rank,  g_rank);
    cudaGetSymbolAddress((void**)&p_list,  g_list);
    cudaGetSymbolAddress((void**)&p_mc,    g_mc);
    cudaGetSymbolAddress((void**)&p_jt,    g_jt);
    cudaGetSymbolAddress((void**)&p_aes,   g_aes);
    cudaGetSymbolAddress((void**)&p_aer,   g_aer);
    cudaGetSymbolAddress((void**)&p_aep,   g_aep);
    cudaGetSymbolAddress((void**)&p_na,    g_na);

    const int SMEM_GEMM = 256 * LDH * 2;   // 69632 B
    cudaFuncSetAttribute(k_gemm, cudaFuncAttributeMaxDynamicSharedMemorySize, SMEM_GEMM);

    const int T = 256;
    const size_t MATSZ = (size_t)Dc * HCc;

    // ---- weight prep + embeddings ----
    k_wprep<<<dim3(16, 4, 12), dim3(32, 8)>>>(Wl, p_wt);
    k_wprep<<<dim3(16, 4, 12), dim3(32, 8)>>>(Wr, p_wt + 12 * MATSZ);
    k_embed<<<(NC * 32 + T - 1) / T, T>>>(cell_x, (const float4*)cell_emb, (__half2*)p_cell, NC * 32);
    k_embed<<<(NP * 32 + T - 1) / T, T>>>(piece_x, (const float4*)piece_emb, (__half2*)p_piece, NP * 32);

    // ---- degrees + CSR + compaction (edges static) ----
    DegB db;
    int Emax = 0;
    for (int r = 0; r < 3; r++) {
        db.dst[r] = dsts[r]; db.src[r] = srcs[r]; db.E[r] = Es[r];
        if (Es[r] > Emax) Emax = Es[r];
    }
    k_zero4<<<(3 * NCc / 4 + T - 1) / T, T>>>((float4*)p_deg, 3 * NCc / 4);
    k_zero4<<<(3 * NCc / 4 + T - 1) / T, T>>>((float4*)p_cur, 3 * NCc / 4);
    k_zero4<<<(3 * NCc * Hc / 4 + T - 1) / T, T>>>((float4*)p_den, 3 * NCc * Hc / 4);
    k_hist<<<dim3((Emax + T - 1) / T, 1, 3), T>>>(db, p_deg);
    k_jt_init<<<1, 1>>>(p_jt, p_na);
    k_scan_all<<<3, 1024>>>(p_deg, p_rs, p_rank, p_list, p_mc, p_jt);
    ScatB sbb;
    for (int r = 0; r < 3; r++) {
        sbb.dst[r] = dsts[r]; sbb.src[r] = srcs[r];
        sbb.deg[r]  = p_deg  + (size_t)r * NCc;
        sbb.rank[r] = p_rank + (size_t)r * NCc;
        sbb.rs[r]   = p_rs   + (size_t)r * (NCc + 1);
        sbb.cur[r]  = p_cur  + (size_t)r * NCc;
        sbb.csrc[r] = p_csrc + (size_t)r * EMAXc;
        sbb.aes[r]  = p_aes  + (size_t)r * EMAXc;
        sbb.aer[r]  = p_aer  + (size_t)r * EMAXc;
        sbb.aep[r]  = p_aep  + (size_t)r * EMAXc;
        sbb.E[r] = Es[r];
    }
    sbb.na = p_na;
    k_scatter<<<dim3((Emax + T - 1) / T, 1, 3), T>>>(sbb);

    // ---- layers ----
    for (int l = 0; l < Lc; l++) {
        GemmBatch gb;
        for (int z = 0; z < 6; z++) {
            int r = (z == 0 || z == 1) ? 0 : (z <= 3 ? 1 : 2);
            bool isL = (z == 0) || (z == 2) || (z == 4);
            int mat = l * 3 + r;
            gb.j[z].A        = (z == 0) ? p_piece : p_cell;
            gb.j[z].W        = p_wt + (isL ? mat : 12 + mat) * MATSZ;
            gb.j[z].bias     = (isL ? bl : br) + (size_t)mat * HCc;
            gb.j[z].out      = isL ? p_xl[r] : p_xr[r];
            gb.j[z].rows     = isL ? nullptr : (p_list + (size_t)r * NCc);
            gb.j[z].tilesPtr = p_jt + z;
            gb.j[z].McPtr    = isL ? nullptr : (p_mc + r);
        }
        k_gemm<<<dim3(4, 64, 6), 256, SMEM_GEMM>>>(gb);

        ScoreB eb;
        for (int r = 0; r < 3; r++) {
            eb.aes[r] = p_aes + (size_t)r * EMAXc;
            eb.aer[r] = p_aer + (size_t)r * EMAXc;
            eb.aep[r] = p_aep + (size_t)r * EMAXc;
            eb.xl[r] = p_xl[r]; eb.xr[r] = p_xr[r];
            eb.att[r] = att + (size_t)(l * 3 + r) * HCc;
            eb.sc[r]  = p_sc  + (size_t)r * EMAXc * Hc;
            eb.den[r] = p_den + (size_t)r * NCc * Hc;
        }
        eb.na = p_na;
        int wpb = T / 32;
        k_scorep<<<dim3((Emax + wpb - 1) / wpb, 1, 3), T>>>(eb);

        AggB ab;
        for (int r = 0; r < 3; r++) {
            ab.rs[r]   = p_rs   + (size_t)r * (NCc + 1);
            ab.csrc[r] = p_csrc + (size_t)r * EMAXc;
            ab.xl[r]   = p_xl[r];
            ab.sc[r]   = p_sc  + (size_t)r * EMAXc * Hc;
            ab.den[r]  = p_den + (size_t)r * NCc * Hc;
            ab.rank[r] = p_rank + (size_t)r * NCc;
        }
        ab.cb   = cb + (size_t)l * 3 * Cc;
        ab.cell = p_cell;
        k_aggr_g<<<NC / 8, 256>>>(ab);
    }

    // ---- pool + heads ----
    k_zero4<<<(Bc * 32 + T - 1) / T, T>>>((float4*)p_sums, Bc * 32);
    k_zero4<<<(Bc / 4 + T - 1) / T, T>>>((float4*)p_cnts, Bc / 4);
    k_pool<<<NC / 64, 128>>>(p_cell, cell_batch, p_sums, p_cnts);

    float* out = (float*)d_out;
    k_head<<<Bc, 64>>>(p_sums, p_cnts, fc1W, fc1b, polW, polb, valW, valb,
                       out, out + (size_t)Bc * BWc);
}